// round 16
// baseline (speedup 1.0000x reference)
#include <cuda_runtime.h>
#include <cuda_fp16.h>
#include <cstdint>

// LinearAttend: q,k,v [4][8][64][8192] f32 -> out same shape.
//   ks = softmax(k, axis=s); qs = softmax(q, axis=d) * D^-0.5
//   ctx = ks @ v^T (64x64/head); out = ctx^T @ qs
// fp16 m16n8k16 MMA (fp32 accum), ldmatrix feed, ex2.approx.f16x2 exps,
// Zk via ones-column MMA, atomic-free split-K partials.
// This round: EXACT r14 kernels (measured 59.9us) + PDL (programmatic
// dependent launch) chaining ctx -> norm -> out to hide launch gaps.

#define SQ 8192
#define DH 64
#define NHEADS 32
#define CHUNKS 8
#define CHUNK_S (SQ / CHUNKS)     // 1024 -> 16 tiles of 64
#define LOG2E 1.4426950408889634f

__device__ float  g_ctx_part[CHUNKS * NHEADS * DH * DH];  // 4 MB partials
__device__ float  g_zk_part[CHUNKS * NHEADS * DH];
__device__ __half g_ctxh[NHEADS * DH * DH];               // normalized ctx

__device__ __forceinline__ uint32_t smem_u32(const void* p) {
    return (uint32_t)__cvta_generic_to_shared(p);
}
__device__ __forceinline__ void cp_async16(uint32_t dst, const void* src) {
    asm volatile("cp.async.cg.shared.global [%0], [%1], 16;" :: "r"(dst), "l"(src));
}
__device__ __forceinline__ void cp_commit() {
    asm volatile("cp.async.commit_group;");
}
__device__ __forceinline__ void cp_wait1() {
    asm volatile("cp.async.wait_group 1;");
}
__device__ __forceinline__ void pdl_launch_dependents() {
    asm volatile("griddepcontrol.launch_dependents;");
}
__device__ __forceinline__ void pdl_wait() {
    asm volatile("griddepcontrol.wait;" ::: "memory");
}
__device__ __forceinline__ void ldsm_x4(uint32_t* r, uint32_t a) {
    asm volatile("ldmatrix.sync.aligned.m8n8.x4.shared.b16 {%0,%1,%2,%3}, [%4];"
                 : "=r"(r[0]), "=r"(r[1]), "=r"(r[2]), "=r"(r[3]) : "r"(a));
}
__device__ __forceinline__ void ldsm_x2(uint32_t* r, uint32_t a) {
    asm volatile("ldmatrix.sync.aligned.m8n8.x2.shared.b16 {%0,%1}, [%2];"
                 : "=r"(r[0]), "=r"(r[1]) : "r"(a));
}
__device__ __forceinline__ void ldsm_x4t(uint32_t* r, uint32_t a) {
    asm volatile("ldmatrix.sync.aligned.m8n8.x4.trans.shared.b16 {%0,%1,%2,%3}, [%4];"
                 : "=r"(r[0]), "=r"(r[1]), "=r"(r[2]), "=r"(r[3]) : "r"(a));
}
__device__ __forceinline__ void mma_f16(float* d, const uint32_t* a, const uint32_t* b) {
    asm volatile(
        "mma.sync.aligned.m16n8k16.row.col.f32.f16.f16.f32 "
        "{%0,%1,%2,%3}, {%4,%5,%6,%7}, {%8,%9}, {%0,%1,%2,%3};"
        : "+f"(d[0]), "+f"(d[1]), "+f"(d[2]), "+f"(d[3])
        : "r"(a[0]), "r"(a[1]), "r"(a[2]), "r"(a[3]), "r"(b[0]), "r"(b[1]));
}
__device__ __forceinline__ uint32_t pack_h2(float hi, float lo) {
    uint32_t h;
    asm("cvt.rn.f16x2.f32 %0, %1, %2;" : "=r"(h) : "f"(hi), "f"(lo));
    return h;
}
__device__ __forceinline__ uint32_t ex2_h2(uint32_t y) {
    uint32_t r;
    asm("ex2.approx.f16x2 %0, %1;" : "=r"(r) : "r"(y));
    return r;
}

// ---------------------------------------------------------------------------
// Kernel 1: ctx partials. grid (CHUNKS, NHEADS), block 256.
// cp.async 2-stage staging, one barrier per tile. (r8/r14 measured-best)
// ---------------------------------------------------------------------------
#define CTX_SVF_OFF 32768
#define CTX_SA_OFF  65536
#define CTX_SB_OFF  83968
#define CTX_SMEM    104704

__global__ __launch_bounds__(256, 2) void ctx_kernel(const float* __restrict__ k,
                                                     const float* __restrict__ v) {
    extern __shared__ char dyn[];
    float* sKf = reinterpret_cast<float*>(dyn);
    float* sVf = reinterpret_cast<float*>(dyn + CTX_SVF_OFF);
    __half (*sAb)[72] = reinterpret_cast<__half(*)[72]>(dyn + CTX_SA_OFF);
    __half (*sBb)[72] = reinterpret_cast<__half(*)[72]>(dyn + CTX_SB_OFF);

    const int head = blockIdx.y;
    const int s0   = blockIdx.x * CHUNK_S;
    const int tid  = threadIdx.x;
    const int warp = tid >> 5;
    const int lane = tid & 31;
    const int wi   = warp & 3;      // i-block (16 rows)
    const int wn   = warp >> 2;     // j-half (32 cols)

    const float* kg = k + (size_t)head * DH * SQ;
    const float* vg = v + (size_t)head * DH * SQ;

    // both B buffers: row 64 = 1.0h (Zk column), rows 65..71 = 0
    for (int e = tid; e < 2 * 8 * 36; e += 256) {
        const int stg = e / (8 * 36);
        const int rem = e % (8 * 36);
        const int row = 64 + rem / 36;
        *reinterpret_cast<uint32_t*>(&sBb[stg * 72 + row][(rem % 36) * 2]) =
            (row == 64) ? 0x3C003C00u : 0u;
    }

    const int r0 = tid >> 4;         // 0..15
    const int c4 = (tid & 15) * 4;   // 0..60

#pragma unroll
    for (int st = 0; st < 2; ++st) {
        const int scol = s0 + st * 64 + c4;
#pragma unroll
        for (int ib = 0; ib < 4; ++ib) {
            const int row = ib * 16 + r0;
            cp_async16(smem_u32(sKf + st * 4096 + row * 64 + c4), kg + (size_t)row * SQ + scol);
            cp_async16(smem_u32(sVf + st * 4096 + row * 64 + c4), vg + (size_t)row * SQ + scol);
        }
        cp_commit();
    }

    float acc[4][4];
#pragma unroll
    for (int n = 0; n < 4; ++n)
#pragma unroll
        for (int c = 0; c < 4; ++c) acc[n][c] = 0.0f;
    float accz[4] = {0.f, 0.f, 0.f, 0.f};

    const int NT = CHUNK_S / 64;    // 16
    for (int t = 0; t < NT; ++t) {
        const int st = t & 1;
        __half (*sA)[72] = sAb + st * 64;
        __half (*sB)[72] = sBb + st * 72;

        cp_wait1();                  // this thread's staged rows landed

        const float* kf = sKf + st * 4096;
        const float* vf = sVf + st * 4096;
#pragma unroll
        for (int ib = 0; ib < 4; ++ib) {
            const int row = ib * 16 + r0;
            float4 kv = *reinterpret_cast<const float4*>(kf + row * 64 + c4);
            float4 vv = *reinterpret_cast<const float4*>(vf + row * 64 + c4);
            uint2 ek;
            ek.x = ex2_h2(pack_h2(kv.y * LOG2E, kv.x * LOG2E));
            ek.y = ex2_h2(pack_h2(kv.w * LOG2E, kv.z * LOG2E));
            *reinterpret_cast<uint2*>(&sA[row][c4]) = ek;
            uint2 vh;
            vh.x = pack_h2(vv.y, vv.x);
            vh.y = pack_h2(vv.w, vv.z);
            *reinterpret_cast<uint2*>(&sB[row][c4]) = vh;
        }

        if (t + 2 < NT) {
            const int scol = s0 + (t + 2) * 64 + c4;
#pragma unroll
            for (int ib = 0; ib < 4; ++ib) {
                const int row = ib * 16 + r0;
                cp_async16(smem_u32(sKf + st * 4096 + row * 64 + c4), kg + (size_t)row * SQ + scol);
                cp_async16(smem_u32(sVf + st * 4096 + row * 64 + c4), vg + (size_t)row * SQ + scol);
            }
        }
        cp_commit();

        __syncthreads();             // the ONE barrier per tile

#pragma unroll
        for (int kk = 0; kk < 4; ++kk) {
            uint32_t a[4];
            ldsm_x4(a, smem_u32(&sA[wi * 16 + (lane & 15)]
                                  [kk * 16 + (lane >> 4) * 8]));
#pragma unroll
            for (int np = 0; np < 2; ++np) {
                uint32_t b[4];
                ldsm_x4(b, smem_u32(&sB[wn * 32 + (np * 2 + (lane >> 4)) * 8 + (lane & 7)]
                                      [kk * 16 + ((lane >> 3) & 1) * 8]));
                mma_f16(acc[np * 2],     a, b);
                mma_f16(acc[np * 2 + 1], a, b + 2);
            }
            if (wn == 1) {
                uint32_t b2[2];
                ldsm_x2(b2, smem_u32(&sB[64 + (lane & 7)]
                                       [kk * 16 + ((lane >> 3) & 1) * 8]));
                mma_f16(accz, a, b2);
            }
        }
    }

    // let dependent grids begin launching while we store partials and exit
    pdl_launch_dependents();

    // store this chunk's partials (no atomics)
    float* ctxp = g_ctx_part + ((size_t)blockIdx.x * NHEADS + head) * DH * DH;
    const int i0 = wi * 16 + (lane >> 2);
    const int jb = wn * 32 + (lane & 3) * 2;
#pragma unroll
    for (int n = 0; n < 4; ++n) {
        const int j = jb + n * 8;
        *reinterpret_cast<float2*>(&ctxp[i0 * 64 + j])       = make_float2(acc[n][0], acc[n][1]);
        *reinterpret_cast<float2*>(&ctxp[(i0 + 8) * 64 + j]) = make_float2(acc[n][2], acc[n][3]);
    }
    if (wn == 1 && (lane & 3) == 0) {
        float* zkp = g_zk_part + ((size_t)blockIdx.x * NHEADS + head) * DH;
        zkp[i0]     = accz[0];
        zkp[i0 + 8] = accz[2];
    }
}

// ---------------------------------------------------------------------------
// Kernel 1.5: sum partials, normalize: ctxh[i][j] = sum_c part[c]*0.125/Zk[i]
// grid (8, NHEADS), block 128. (r14 wide version)
// ---------------------------------------------------------------------------
__global__ __launch_bounds__(128) void norm_kernel() {
    pdl_wait();                      // full-completion wait on ctx_kernel
    pdl_launch_dependents();         // let out_kernel begin launching

    const int head = blockIdx.y;
    const int rblk = blockIdx.x;               // 8-row block
    const int tid  = threadIdx.x;
    const int base = rblk * 8 * 64 + tid * 4;  // element offset within head
    const int i    = base >> 6;                // row

    float z = 0.0f;
#pragma unroll
    for (int c = 0; c < CHUNKS; ++c)
        z += g_zk_part[((size_t)c * NHEADS + head) * DH + i];
    const float inv = __fdividef(0.125f, z);

    float4 s = make_float4(0.f, 0.f, 0.f, 0.f);
#pragma unroll
    for (int c = 0; c < CHUNKS; ++c) {
        const float* p = g_ctx_part + ((size_t)c * NHEADS + head) * DH * DH + base;
        float4 f = *reinterpret_cast<const float4*>(p);
        s.x += f.x; s.y += f.y; s.z += f.z; s.w += f.w;
    }
    uint2 o;
    o.x = pack_h2(s.y * inv, s.x * inv);
    o.y = pack_h2(s.w * inv, s.z * inv);
    *reinterpret_cast<uint2*>(g_ctxh + head * DH * DH + base) = o;
}

// ---------------------------------------------------------------------------
// Kernel 2: out[j,s] = (1/Zq_s) * sum_i ctxh[i][j] * exp(q[i,s])
// grid (SQ/128, NHEADS), block 256, one 64j x 128s tile per CTA.
// (r8/r14 measured-best shape: 26.0us)
// ---------------------------------------------------------------------------
__global__ __launch_bounds__(256, 4) void out_kernel(const float* __restrict__ q,
                                                     float* __restrict__ out) {
    __shared__ __half sCt[64][72];    // [i][j] normalized half context
    __shared__ __half sQ[64][136];    // [i][s] exp(q) half
    __shared__ float  sZp[8][132];    // Zq partials
    __shared__ float  sCs[128];       // 1/Zq_s

    pdl_wait();                       // full-completion wait on norm_kernel

    const int head = blockIdx.y;
    const int s0   = blockIdx.x * 128;
    const int tid  = threadIdx.x;
    const int warp = tid >> 5;
    const int lane = tid & 31;

    const float* qg = q + (size_t)head * DH * SQ + s0;
    const int r  = tid >> 5;          // 0..7
    const int c4 = (tid & 31) * 4;    // 0..124

    // context tile: 256 threads x 2 uint4 = 8 KB (hits L2)
    {
        const uint4* src = reinterpret_cast<const uint4*>(g_ctxh + head * DH * DH);
        uint4 c0 = src[tid * 2];
        uint4 c1 = src[tid * 2 + 1];
        const int i = tid >> 2;
        const int j = (tid & 3) * 16;
        *reinterpret_cast<uint4*>(&sCt[i][j])     = c0;
        *reinterpret_cast<uint4*>(&sCt[i][j + 8]) = c1;
    }

    // q: two batches of 4 float4 (bounded register pressure)
    float4 zp = make_float4(0.f, 0.f, 0.f, 0.f);
#pragma unroll
    for (int half = 0; half < 2; ++half) {
        float4 qv[4];
#pragma unroll
        for (int ib = 0; ib < 4; ++ib) {
            const int d = (half * 4 + ib) * 8 + r;
            qv[ib] = *reinterpret_cast<const float4*>(qg + (size_t)d * SQ + c4);
        }
#pragma unroll
        for (int ib = 0; ib < 4; ++ib) {
            const int d = (half * 4 + ib) * 8 + r;
            uint2 eq;
            eq.x = ex2_h2(pack_h2(qv[ib].y * LOG2E, qv[ib].x * LOG2E));
            eq.y = ex2_h2(pack_h2(qv[ib].w * LOG2E, qv[ib].z * LOG2E));
            *reinterpret_cast<uint2*>(&sQ[d][c4]) = eq;
            float2 e0 = __half22float2(*reinterpret_cast<__half2*>(&eq.x));
            float2 e1 = __half22float2(*reinterpret_cast<__half2*>(&eq.y));
            zp.x += e0.x; zp.y += e0.y; zp.z += e1.x; zp.w += e1.y;
        }
    }
    *reinterpret_cast<float4*>(&sZp[r][c4]) = zp;
    __syncthreads();

    if (tid < 128) {
        float z = 0.0f;
#pragma unroll
        for (int d = 0; d < 8; ++d) z += sZp[d][tid];
        sCs[tid] = __fdividef(1.0f, z);
    }

    float acc[8][4];
#pragma unroll
    for (int n = 0; n < 8; ++n)
#pragma unroll
        for (int c = 0; c < 4; ++c) acc[n][c] = 0.0f;

    const int jw = (warp & 3) * 16;   // j offset
    const int sw = (warp >> 2) * 64;  // s offset

#pragma unroll
    for (int kk = 0; kk < 4; ++kk) {
        uint32_t a[4];
        ldsm_x4t(a, smem_u32(&sCt[kk * 16 + (lane & 7) + (lane >> 4) * 8]
                                [jw + ((lane >> 3) & 1) * 8]));
#pragma unroll
        for (int np = 0; np < 4; ++np) {
            uint32_t b[4];
            ldsm_x4t(b, smem_u32(&sQ[kk * 16 + (lane & 7) + ((lane >> 3) & 1) * 8]
                                    [sw + (np * 2 + (lane >> 4)) * 8]));
            mma_f16(acc[np * 2],     a, b);
            mma_f16(acc[np * 2 + 1], a, b + 2);
        }
    }
    __syncthreads();   // sCs ready (reduce overlapped with MMA issue)

    float* og = out + (size_t)head * DH * SQ + s0;
    const int j0 = jw + (lane >> 2);
    const int sc = (lane & 3) * 2;
#pragma unroll
    for (int n = 0; n < 8; ++n) {
        const int s = sw + n * 8 + sc;
        const float inv0 = sCs[s];
        const float inv1 = sCs[s + 1];
        float2 w0 = make_float2(acc[n][0] * inv0, acc[n][1] * inv1);
        float2 w1 = make_float2(acc[n][2] * inv0, acc[n][3] * inv1);
        *reinterpret_cast<float2*>(og + (size_t)j0 * SQ + s) = w0;
        *reinterpret_cast<float2*>(og + (size_t)(j0 + 8) * SQ + s) = w1;
    }
}

// ---------------------------------------------------------------------------
extern "C" void kernel_launch(void* const* d_in, const int* in_sizes, int n_in,
                              void* d_out, int out_size) {
    const float* q = (const float*)d_in[0];
    const float* k = (const float*)d_in[1];
    const float* v = (const float*)d_in[2];
    float* out = (float*)d_out;

    cudaFuncSetAttribute(ctx_kernel, cudaFuncAttributeMaxDynamicSharedMemorySize, CTX_SMEM);

    ctx_kernel<<<dim3(CHUNKS, NHEADS), 256, CTX_SMEM>>>(k, v);

    // norm: PDL-chained to ctx
    {
        cudaLaunchConfig_t cfg = {};
        cfg.gridDim  = dim3(8, NHEADS, 1);
        cfg.blockDim = dim3(128, 1, 1);
        cudaLaunchAttribute attr[1];
        attr[0].id = cudaLaunchAttributeProgrammaticStreamSerialization;
        attr[0].val.programmaticStreamSerializationAllowed = 1;
        cfg.attrs = attr;
        cfg.numAttrs = 1;
        cudaLaunchKernelEx(&cfg, norm_kernel);
    }

    // out: PDL-chained to norm
    {
        cudaLaunchConfig_t cfg = {};
        cfg.gridDim  = dim3(SQ / 128, NHEADS, 1);
        cfg.blockDim = dim3(256, 1, 1);
        cudaLaunchAttribute attr[1];
        attr[0].id = cudaLaunchAttributeProgrammaticStreamSerialization;
        attr[0].val.programmaticStreamSerializationAllowed = 1;
        cfg.attrs = attr;
        cfg.numAttrs = 1;
        cudaLaunchKernelEx(&cfg, out_kernel, q, out);
    }
}

// round 17
// speedup vs baseline: 1.2405x; 1.2405x over previous
#include <cuda_runtime.h>
#include <cuda_fp16.h>
#include <cstdint>

// LinearAttend: q,k,v [4][8][64][8192] f32 -> out same shape.
//   ks = softmax(k, axis=s); qs = softmax(q, axis=d) * D^-0.5
//   ctx = ks @ v^T (64x64/head); out = ctx^T @ qs
// fp16 m16n8k16 MMA (fp32 accum), ldmatrix feed, ex2.approx.f16x2 exps,
// Zk via ones-column MMA, atomic-free split-K partials.
// This round: PDL reverted (regressed). ctx + norm byte-identical to r14
// (59.9us). out re-tiled 16jx64s -> 32jx32s per warp: 20 -> 16 ldsm per
// warp-tile and B-operand redundancy halved (out is L1-bound at 69.5%).

#define SQ 8192
#define DH 64
#define NHEADS 32
#define CHUNKS 8
#define CHUNK_S (SQ / CHUNKS)     // 1024 -> 16 tiles of 64
#define LOG2E 1.4426950408889634f

__device__ float  g_ctx_part[CHUNKS * NHEADS * DH * DH];  // 4 MB partials
__device__ float  g_zk_part[CHUNKS * NHEADS * DH];
__device__ __half g_ctxh[NHEADS * DH * DH];               // normalized ctx

__device__ __forceinline__ uint32_t smem_u32(const void* p) {
    return (uint32_t)__cvta_generic_to_shared(p);
}
__device__ __forceinline__ void cp_async16(uint32_t dst, const void* src) {
    asm volatile("cp.async.cg.shared.global [%0], [%1], 16;" :: "r"(dst), "l"(src));
}
__device__ __forceinline__ void cp_commit() {
    asm volatile("cp.async.commit_group;");
}
__device__ __forceinline__ void cp_wait1() {
    asm volatile("cp.async.wait_group 1;");
}
__device__ __forceinline__ void ldsm_x4(uint32_t* r, uint32_t a) {
    asm volatile("ldmatrix.sync.aligned.m8n8.x4.shared.b16 {%0,%1,%2,%3}, [%4];"
                 : "=r"(r[0]), "=r"(r[1]), "=r"(r[2]), "=r"(r[3]) : "r"(a));
}
__device__ __forceinline__ void ldsm_x2(uint32_t* r, uint32_t a) {
    asm volatile("ldmatrix.sync.aligned.m8n8.x2.shared.b16 {%0,%1}, [%2];"
                 : "=r"(r[0]), "=r"(r[1]) : "r"(a));
}
__device__ __forceinline__ void ldsm_x4t(uint32_t* r, uint32_t a) {
    asm volatile("ldmatrix.sync.aligned.m8n8.x4.trans.shared.b16 {%0,%1,%2,%3}, [%4];"
                 : "=r"(r[0]), "=r"(r[1]), "=r"(r[2]), "=r"(r[3]) : "r"(a));
}
__device__ __forceinline__ void mma_f16(float* d, const uint32_t* a, const uint32_t* b) {
    asm volatile(
        "mma.sync.aligned.m16n8k16.row.col.f32.f16.f16.f32 "
        "{%0,%1,%2,%3}, {%4,%5,%6,%7}, {%8,%9}, {%0,%1,%2,%3};"
        : "+f"(d[0]), "+f"(d[1]), "+f"(d[2]), "+f"(d[3])
        : "r"(a[0]), "r"(a[1]), "r"(a[2]), "r"(a[3]), "r"(b[0]), "r"(b[1]));
}
__device__ __forceinline__ uint32_t pack_h2(float hi, float lo) {
    uint32_t h;
    asm("cvt.rn.f16x2.f32 %0, %1, %2;" : "=r"(h) : "f"(hi), "f"(lo));
    return h;
}
__device__ __forceinline__ uint32_t ex2_h2(uint32_t y) {
    uint32_t r;
    asm("ex2.approx.f16x2 %0, %1;" : "=r"(r) : "r"(y));
    return r;
}

// ---------------------------------------------------------------------------
// Kernel 1: ctx partials. grid (CHUNKS, NHEADS), block 256.
// cp.async 2-stage staging, one barrier per tile. (r8/r14 measured-best)
// ---------------------------------------------------------------------------
#define CTX_SVF_OFF 32768
#define CTX_SA_OFF  65536
#define CTX_SB_OFF  83968
#define CTX_SMEM    104704

__global__ __launch_bounds__(256, 2) void ctx_kernel(const float* __restrict__ k,
                                                     const float* __restrict__ v) {
    extern __shared__ char dyn[];
    float* sKf = reinterpret_cast<float*>(dyn);
    float* sVf = reinterpret_cast<float*>(dyn + CTX_SVF_OFF);
    __half (*sAb)[72] = reinterpret_cast<__half(*)[72]>(dyn + CTX_SA_OFF);
    __half (*sBb)[72] = reinterpret_cast<__half(*)[72]>(dyn + CTX_SB_OFF);

    const int head = blockIdx.y;
    const int s0   = blockIdx.x * CHUNK_S;
    const int tid  = threadIdx.x;
    const int warp = tid >> 5;
    const int lane = tid & 31;
    const int wi   = warp & 3;      // i-block (16 rows)
    const int wn   = warp >> 2;     // j-half (32 cols)

    const float* kg = k + (size_t)head * DH * SQ;
    const float* vg = v + (size_t)head * DH * SQ;

    // both B buffers: row 64 = 1.0h (Zk column), rows 65..71 = 0
    for (int e = tid; e < 2 * 8 * 36; e += 256) {
        const int stg = e / (8 * 36);
        const int rem = e % (8 * 36);
        const int row = 64 + rem / 36;
        *reinterpret_cast<uint32_t*>(&sBb[stg * 72 + row][(rem % 36) * 2]) =
            (row == 64) ? 0x3C003C00u : 0u;
    }

    const int r0 = tid >> 4;         // 0..15
    const int c4 = (tid & 15) * 4;   // 0..60

#pragma unroll
    for (int st = 0; st < 2; ++st) {
        const int scol = s0 + st * 64 + c4;
#pragma unroll
        for (int ib = 0; ib < 4; ++ib) {
            const int row = ib * 16 + r0;
            cp_async16(smem_u32(sKf + st * 4096 + row * 64 + c4), kg + (size_t)row * SQ + scol);
            cp_async16(smem_u32(sVf + st * 4096 + row * 64 + c4), vg + (size_t)row * SQ + scol);
        }
        cp_commit();
    }

    float acc[4][4];
#pragma unroll
    for (int n = 0; n < 4; ++n)
#pragma unroll
        for (int c = 0; c < 4; ++c) acc[n][c] = 0.0f;
    float accz[4] = {0.f, 0.f, 0.f, 0.f};

    const int NT = CHUNK_S / 64;    // 16
    for (int t = 0; t < NT; ++t) {
        const int st = t & 1;
        __half (*sA)[72] = sAb + st * 64;
        __half (*sB)[72] = sBb + st * 72;

        cp_wait1();                  // this thread's staged rows landed

        const float* kf = sKf + st * 4096;
        const float* vf = sVf + st * 4096;
#pragma unroll
        for (int ib = 0; ib < 4; ++ib) {
            const int row = ib * 16 + r0;
            float4 kv = *reinterpret_cast<const float4*>(kf + row * 64 + c4);
            float4 vv = *reinterpret_cast<const float4*>(vf + row * 64 + c4);
            uint2 ek;
            ek.x = ex2_h2(pack_h2(kv.y * LOG2E, kv.x * LOG2E));
            ek.y = ex2_h2(pack_h2(kv.w * LOG2E, kv.z * LOG2E));
            *reinterpret_cast<uint2*>(&sA[row][c4]) = ek;
            uint2 vh;
            vh.x = pack_h2(vv.y, vv.x);
            vh.y = pack_h2(vv.w, vv.z);
            *reinterpret_cast<uint2*>(&sB[row][c4]) = vh;
        }

        if (t + 2 < NT) {
            const int scol = s0 + (t + 2) * 64 + c4;
#pragma unroll
            for (int ib = 0; ib < 4; ++ib) {
                const int row = ib * 16 + r0;
                cp_async16(smem_u32(sKf + st * 4096 + row * 64 + c4), kg + (size_t)row * SQ + scol);
                cp_async16(smem_u32(sVf + st * 4096 + row * 64 + c4), vg + (size_t)row * SQ + scol);
            }
        }
        cp_commit();

        __syncthreads();             // the ONE barrier per tile

#pragma unroll
        for (int kk = 0; kk < 4; ++kk) {
            uint32_t a[4];
            ldsm_x4(a, smem_u32(&sA[wi * 16 + (lane & 15)]
                                  [kk * 16 + (lane >> 4) * 8]));
#pragma unroll
            for (int np = 0; np < 2; ++np) {
                uint32_t b[4];
                ldsm_x4(b, smem_u32(&sB[wn * 32 + (np * 2 + (lane >> 4)) * 8 + (lane & 7)]
                                      [kk * 16 + ((lane >> 3) & 1) * 8]));
                mma_f16(acc[np * 2],     a, b);
                mma_f16(acc[np * 2 + 1], a, b + 2);
            }
            if (wn == 1) {
                uint32_t b2[2];
                ldsm_x2(b2, smem_u32(&sB[64 + (lane & 7)]
                                       [kk * 16 + ((lane >> 3) & 1) * 8]));
                mma_f16(accz, a, b2);
            }
        }
    }

    // store this chunk's partials (no atomics)
    float* ctxp = g_ctx_part + ((size_t)blockIdx.x * NHEADS + head) * DH * DH;
    const int i0 = wi * 16 + (lane >> 2);
    const int jb = wn * 32 + (lane & 3) * 2;
#pragma unroll
    for (int n = 0; n < 4; ++n) {
        const int j = jb + n * 8;
        *reinterpret_cast<float2*>(&ctxp[i0 * 64 + j])       = make_float2(acc[n][0], acc[n][1]);
        *reinterpret_cast<float2*>(&ctxp[(i0 + 8) * 64 + j]) = make_float2(acc[n][2], acc[n][3]);
    }
    if (wn == 1 && (lane & 3) == 0) {
        float* zkp = g_zk_part + ((size_t)blockIdx.x * NHEADS + head) * DH;
        zkp[i0]     = accz[0];
        zkp[i0 + 8] = accz[2];
    }
}

// ---------------------------------------------------------------------------
// Kernel 1.5: sum partials, normalize: ctxh[i][j] = sum_c part[c]*0.125/Zk[i]
// grid (8, NHEADS), block 128. (r14 wide version)
// ---------------------------------------------------------------------------
__global__ __launch_bounds__(128) void norm_kernel() {
    const int head = blockIdx.y;
    const int rblk = blockIdx.x;               // 8-row block
    const int tid  = threadIdx.x;
    const int base = rblk * 8 * 64 + tid * 4;  // element offset within head
    const int i    = base >> 6;                // row

    float z = 0.0f;
#pragma unroll
    for (int c = 0; c < CHUNKS; ++c)
        z += g_zk_part[((size_t)c * NHEADS + head) * DH + i];
    const float inv = __fdividef(0.125f, z);

    float4 s = make_float4(0.f, 0.f, 0.f, 0.f);
#pragma unroll
    for (int c = 0; c < CHUNKS; ++c) {
        const float* p = g_ctx_part + ((size_t)c * NHEADS + head) * DH * DH + base;
        float4 f = *reinterpret_cast<const float4*>(p);
        s.x += f.x; s.y += f.y; s.z += f.z; s.w += f.w;
    }
    uint2 o;
    o.x = pack_h2(s.y * inv, s.x * inv);
    o.y = pack_h2(s.w * inv, s.z * inv);
    *reinterpret_cast<uint2*>(g_ctxh + head * DH * DH + base) = o;
}

// ---------------------------------------------------------------------------
// Kernel 2: out[j,s] = (1/Zq_s) * sum_i ctxh[i][j] * exp(q[i,s])
// grid (SQ/128, NHEADS), block 256, one 64j x 128s tile per CTA.
// Warp tile 32j x 32s (2-way j, 4-way s): 16 ldsm/warp-tile instead of 20,
// B redundancy halved. Everything else identical to r14.
// ---------------------------------------------------------------------------
__global__ __launch_bounds__(256, 4) void out_kernel(const float* __restrict__ q,
                                                     float* __restrict__ out) {
    __shared__ __half sCt[64][72];    // [i][j] normalized half context
    __shared__ __half sQ[64][136];    // [i][s] exp(q) half
    __shared__ float  sZp[8][132];    // Zq partials
    __shared__ float  sCs[128];       // 1/Zq_s

    const int head = blockIdx.y;
    const int s0   = blockIdx.x * 128;
    const int tid  = threadIdx.x;
    const int warp = tid >> 5;
    const int lane = tid & 31;

    const float* qg = q + (size_t)head * DH * SQ + s0;
    const int r  = tid >> 5;          // 0..7
    const int c4 = (tid & 31) * 4;    // 0..124

    // context tile: 256 threads x 2 uint4 = 8 KB (hits L2)
    {
        const uint4* src = reinterpret_cast<const uint4*>(g_ctxh + head * DH * DH);
        uint4 c0 = src[tid * 2];
        uint4 c1 = src[tid * 2 + 1];
        const int i = tid >> 2;
        const int j = (tid & 3) * 16;
        *reinterpret_cast<uint4*>(&sCt[i][j])     = c0;
        *reinterpret_cast<uint4*>(&sCt[i][j + 8]) = c1;
    }

    // q: two batches of 4 float4 (bounded register pressure)
    float4 zp = make_float4(0.f, 0.f, 0.f, 0.f);
#pragma unroll
    for (int half = 0; half < 2; ++half) {
        float4 qv[4];
#pragma unroll
        for (int ib = 0; ib < 4; ++ib) {
            const int d = (half * 4 + ib) * 8 + r;
            qv[ib] = *reinterpret_cast<const float4*>(qg + (size_t)d * SQ + c4);
        }
#pragma unroll
        for (int ib = 0; ib < 4; ++ib) {
            const int d = (half * 4 + ib) * 8 + r;
            uint2 eq;
            eq.x = ex2_h2(pack_h2(qv[ib].y * LOG2E, qv[ib].x * LOG2E));
            eq.y = ex2_h2(pack_h2(qv[ib].w * LOG2E, qv[ib].z * LOG2E));
            *reinterpret_cast<uint2*>(&sQ[d][c4]) = eq;
            float2 e0 = __half22float2(*reinterpret_cast<__half2*>(&eq.x));
            float2 e1 = __half22float2(*reinterpret_cast<__half2*>(&eq.y));
            zp.x += e0.x; zp.y += e0.y; zp.z += e1.x; zp.w += e1.y;
        }
    }
    *reinterpret_cast<float4*>(&sZp[r][c4]) = zp;
    __syncthreads();

    if (tid < 128) {
        float z = 0.0f;
#pragma unroll
        for (int d = 0; d < 8; ++d) z += sZp[d][tid];
        sCs[tid] = __fdividef(1.0f, z);
    }

    float acc[2][4][4];               // [j-frag][n-block][frag]
#pragma unroll
    for (int ja = 0; ja < 2; ++ja)
#pragma unroll
        for (int n = 0; n < 4; ++n)
#pragma unroll
            for (int c = 0; c < 4; ++c) acc[ja][n][c] = 0.0f;

    const int jw = (warp & 1) * 32;   // j offset (2-way split)
    const int sw = (warp >> 1) * 32;  // s offset (4-way split)

#pragma unroll
    for (int kk = 0; kk < 4; ++kk) {
        uint32_t a[2][4];
#pragma unroll
        for (int ja = 0; ja < 2; ++ja)
            ldsm_x4t(a[ja], smem_u32(&sCt[kk * 16 + (lane & 7) + (lane >> 4) * 8]
                                        [jw + ja * 16 + ((lane >> 3) & 1) * 8]));
#pragma unroll
        for (int nb = 0; nb < 2; ++nb) {
            uint32_t b[4];
            ldsm_x4t(b, smem_u32(&sQ[kk * 16 + (lane & 7) + ((lane >> 3) & 1) * 8]
                                    [sw + (nb * 2 + (lane >> 4)) * 8]));
#pragma unroll
            for (int ja = 0; ja < 2; ++ja) {
                mma_f16(acc[ja][nb * 2],     a[ja], b);
                mma_f16(acc[ja][nb * 2 + 1], a[ja], b + 2);
            }
        }
    }
    __syncthreads();   // sCs ready (reduce overlapped with MMA issue)

    float* og = out + (size_t)head * DH * SQ + s0;
    const int sc = (lane & 3) * 2;
#pragma unroll
    for (int ja = 0; ja < 2; ++ja) {
        const int j0 = jw + ja * 16 + (lane >> 2);
#pragma unroll
        for (int n = 0; n < 4; ++n) {
            const int s = sw + n * 8 + sc;
            const float inv0 = sCs[s];
            const float inv1 = sCs[s + 1];
            float2 w0 = make_float2(acc[ja][n][0] * inv0, acc[ja][n][1] * inv1);
            float2 w1 = make_float2(acc[ja][n][2] * inv0, acc[ja][n][3] * inv1);
            *reinterpret_cast<float2*>(og + (size_t)j0 * SQ + s) = w0;
            *reinterpret_cast<float2*>(og + (size_t)(j0 + 8) * SQ + s) = w1;
        }
    }
}

// ---------------------------------------------------------------------------
extern "C" void kernel_launch(void* const* d_in, const int* in_sizes, int n_in,
                              void* d_out, int out_size) {
    const float* q = (const float*)d_in[0];
    const float* k = (const float*)d_in[1];
    const float* v = (const float*)d_in[2];
    float* out = (float*)d_out;

    cudaFuncSetAttribute(ctx_kernel, cudaFuncAttributeMaxDynamicSharedMemorySize, CTX_SMEM);

    ctx_kernel<<<dim3(CHUNKS, NHEADS), 256, CTX_SMEM>>>(k, v);
    norm_kernel<<<dim3(8, NHEADS), 128>>>();
    out_kernel<<<dim3(SQ / 128, NHEADS), 256>>>(q, out);
}